// round 16
// baseline (speedup 1.0000x reference)
#include <cuda_runtime.h>
#include <cuda_fp16.h>
#include <cstdint>

// ---------------------------------------------------------------------------
// out[t,o] = sum_i (x[t,i]*scales[i]) * W[o,i]
//   x [32,4096] f32, W [14336,4096] int32 (int8-valued), scales [4096] f32
//   out [32,14336] f32
//
// R15: R14 (32x32 warp tiles, LDSM bytes = 1.0x W bytes, KSPLIT=4 with
// deterministic ticket-serialized epilogue) with the odd-chunk swizzle fix:
// second k-half store is (wsts0 + p*4096) ^ 64 — XOR, not +64. wsts0 bit 6
// carries row-bit-2 from the SW128 fold, so arithmetic +64 carried into
// bit 7 for half the rows (same bug class as R7).
// TILE_M=128, 128 thr, KC=32 (2 chunks per 128B SMEM row), double buffer,
// 1 barrier/chunk, 448 CTAs (4/SM, all resident).
// ---------------------------------------------------------------------------

#define SWZ(off) ((off) ^ (((off) >> 3) & 0x70))

static constexpr int TOKENS = 32;
static constexpr int INF    = 4096;
static constexpr int OUTF   = 14336;
static constexpr int TILE_M = 128;
static constexpr int NTHR   = 128;
static constexpr int KSPLIT = 4;
static constexpr int KQ     = INF / KSPLIT;   // 1024
static constexpr int KC     = 32;             // K elements per chunk
static constexpr int NITER  = KQ / KC;        // 32
static constexpr int NPAIR  = NITER / 2;      // 16
static constexpr int NTILES = OUTF / TILE_M;  // 112

// SMEM: W pair-buffers (128 rows x 128B = 2 chunks/row) + xs pair-buffers
static constexpr int WBUF  = TILE_M * 128;        // 16384
static constexpr int XOFF  = 2 * WBUF;            // 32768
static constexpr int XBUF  = TOKENS * 128;        // 4096
static constexpr int SMEM_TOTAL = XOFF + 2 * XBUF; // 40960

static constexpr int W_P = 32 * INF * 4;      // +32 rows (bytes)
static constexpr int X_P = 16 * INF * 2;      // +16 tokens (bytes)

// fp16 scaled activations + split-K tickets
__device__ __align__(16) __half g_xs[TOKENS * INF];
__device__ int g_ticket[NTILES];              // zero-init; self-resetting

// ---------------- helpers ----------------
__device__ __forceinline__ uint32_t smem_u32(const void* p) {
    uint32_t a;
    asm("{ .reg .u64 t; cvta.to.shared.u64 t, %1; cvt.u32.u64 %0, t; }"
        : "=r"(a) : "l"(p));
    return a;
}

__device__ __forceinline__ void sts128(uint32_t addr, uint32_t r0, uint32_t r1,
                                       uint32_t r2, uint32_t r3) {
    asm volatile("st.shared.v4.b32 [%0], {%1, %2, %3, %4};"
                 :: "r"(addr), "r"(r0), "r"(r1), "r"(r2), "r"(r3) : "memory");
}

__device__ __forceinline__ void cp16(uint32_t dst, const void* src) {
    asm volatile("cp.async.cg.shared.global [%0], [%1], 16;"
                 :: "r"(dst), "l"(src) : "memory");
}
__device__ __forceinline__ void cp_commit() {
    asm volatile("cp.async.commit_group;" ::: "memory");
}
__device__ __forceinline__ void cp_wait0() {
    asm volatile("cp.async.wait_group 0;" ::: "memory");
}

// pack two ints (|v|<=127, exact in fp16) -> half2 bits
__device__ __forceinline__ uint32_t packhf(int a, int b) {
    __half2 h = __floats2half2_rn((float)a, (float)b);
    return *reinterpret_cast<uint32_t*>(&h);
}

__device__ __forceinline__ void ldsm_x4(uint32_t addr, uint32_t& r0, uint32_t& r1,
                                        uint32_t& r2, uint32_t& r3) {
    asm volatile("ldmatrix.sync.aligned.m8n8.x4.shared.b16 {%0,%1,%2,%3}, [%4];"
                 : "=r"(r0), "=r"(r1), "=r"(r2), "=r"(r3) : "r"(addr));
}

__device__ __forceinline__ void mma_16816(float* d, const uint32_t* a, const uint32_t* b) {
    asm volatile(
        "mma.sync.aligned.m16n8k16.row.col.f32.f16.f16.f32 "
        "{%0,%1,%2,%3}, {%4,%5,%6,%7}, {%8,%9}, {%0,%1,%2,%3};"
        : "+f"(d[0]), "+f"(d[1]), "+f"(d[2]), "+f"(d[3])
        : "r"(a[0]), "r"(a[1]), "r"(a[2]), "r"(a[3]), "r"(b[0]), "r"(b[1]));
}

// one KC=32 chunk: 2 k16 steps, 2 A-frags x 4 B n8-tiles = 8 MMA/step
__device__ __forceinline__ void compute_chunk(uint32_t Wb, uint32_t Xb, int half,
                                              int aOff, int bOff, float (&acc)[8][4]) {
#pragma unroll
    for (int ks = 0; ks < 2; ks++) {
        uint32_t al[4], ah[4], bl[4], bh[4];
        const int ko = half + ks * 32;
        const uint32_t aAddr = Wb + SWZ(aOff + ko);
        const uint32_t bAddr = Xb + SWZ(bOff + ko);
        ldsm_x4(aAddr,        al[0], al[1], al[2], al[3]);
        ldsm_x4(aAddr + 2048, ah[0], ah[1], ah[2], ah[3]);   // +16 rows
        ldsm_x4(bAddr,        bl[0], bl[1], bl[2], bl[3]);
        ldsm_x4(bAddr + 2048, bh[0], bh[1], bh[2], bh[3]);   // +16 tokens
        mma_16816(acc[0], al, bl + 0);
        mma_16816(acc[1], al, bl + 2);
        mma_16816(acc[2], al, bh + 0);
        mma_16816(acc[3], al, bh + 2);
        mma_16816(acc[4], ah, bl + 0);
        mma_16816(acc[5], ah, bl + 2);
        mma_16816(acc[6], ah, bh + 0);
        mma_16816(acc[7], ah, bh + 2);
    }
}

// ---------------- prep: xs = fp16(x*scales) ----------------
__global__ void prep_kernel(const float* __restrict__ x, const float* __restrict__ s) {
    int i = blockIdx.x * blockDim.x + threadIdx.x;
    if (i < TOKENS * INF) {
        int k = i & (INF - 1);
        g_xs[i] = __float2half_rn(x[i] * s[k]);
    }
}

// ---------------- main GEMM ----------------
__global__ void __launch_bounds__(NTHR, 4)
qgemm_kernel(const int* __restrict__ W, float* __restrict__ out) {
    __shared__ __align__(1024) char smem[SMEM_TOTAL];
    const uint32_t sb = smem_u32(smem);
    const int tid = threadIdx.x;
    const int lane = tid & 31;
    const int wid = tid >> 5;                  // 0..3 -> 32-row group

    const int tile = blockIdx.x >> 2;
    const int ksp  = blockIdx.x & 3;
    const int row_base = tile * TILE_M;
    const int kbase = ksp * KQ;

    // ---- W producer: 4 granules (8 ints = 16B fp16); r=tid>>2 (+32p), c=tid&3 ----
    const char* wpB = (const char*)(W + (size_t)(row_base + (tid >> 2)) * INF
                                    + kbase + (tid & 3) * 8);
    const uint32_t wsts0 = SWZ((tid >> 2) * 128 + (tid & 3) * 16);  // +p*4096; ^64 for half 1

    // ---- xs producer: 2 granules per pair; t=tid>>3 (+16p), c=tid&7 ----
    const char* xpB = (const char*)(g_xs + (tid >> 3) * INF + kbase + (tid & 7) * 8);
    const uint32_t xsts0 = SWZ((tid >> 3) * 128 + (tid & 7) * 16);  // +p*2048

    // ---- ldmatrix lane geometry ----
    const int rowA  = wid * 32 + (lane & 7) + (lane & 8);
    const int aCsel = (lane & 16);             // +8 fp16 -> +16B (k+8 tile)
    const int tokB  = (lane & 7) + ((lane & 16) >> 1);
    const int bCsel = (lane & 8) * 2;          // +16B (k+8 tile)
    const int aOff  = rowA * 128 + aCsel;
    const int bOff  = tokB * 128 + bCsel;

    float acc[8][4];                           // [m*4+n][frag]
#pragma unroll
    for (int n = 0; n < 8; n++)
#pragma unroll
        for (int r = 0; r < 4; r++) acc[n][r] = 0.0f;

    int4 w[8];                                 // staged chunk: 4 granules x 2 int4

    // ---- prologue: W chunk 0 -> regs; xs pair 0 -> cp.async ----
#pragma unroll
    for (int p = 0; p < 4; p++) {
        w[2 * p]     = *(const int4*)(wpB + p * W_P);
        w[2 * p + 1] = *(const int4*)(wpB + p * W_P + 16);
    }
    wpB += KC * 4;
    cp16(sb + XOFF + xsts0, xpB);
    cp16(sb + XOFF + xsts0 + 2048, xpB + X_P);
    xpB += 128;                                // +64 k
    cp_commit();

#pragma unroll 1
    for (int m = 0; m < NPAIR; ++m) {
        const uint32_t Wb = sb + (m & 1) * WBUF;
        const uint32_t Xb = sb + XOFF + (m & 1) * XBUF;

        // ===== even chunk 2m -> k-half 0 of each 128B row =====
#pragma unroll
        for (int p = 0; p < 4; p++) {
            int4 u = w[2 * p], v = w[2 * p + 1];
            sts128(Wb + wsts0 + p * 4096,
                   packhf(u.x, u.y), packhf(u.z, u.w),
                   packhf(v.x, v.y), packhf(v.z, v.w));
        }
        // LDG chunk 2m+1 (always valid)
#pragma unroll
        for (int p = 0; p < 4; p++) {
            w[2 * p]     = *(const int4*)(wpB + p * W_P);
            w[2 * p + 1] = *(const int4*)(wpB + p * W_P + 16);
        }
        wpB += KC * 4;

        cp_wait0();        // xs pair m landed
        __syncthreads();   // W half0 + xs visible; pair m-1 compute done

        if (m + 1 < NPAIR) {
            const uint32_t xd = sb + XOFF + ((m + 1) & 1) * XBUF + xsts0;
            cp16(xd, xpB);
            cp16(xd + 2048, xpB + X_P);
            xpB += 128;
            cp_commit();
        }
        compute_chunk(Wb, Xb, 0, aOff, bOff, acc);

        // ===== odd chunk 2m+1 -> k-half 1: XOR 64 (bit 6 may be set by SWZ) =====
#pragma unroll
        for (int p = 0; p < 4; p++) {
            int4 u = w[2 * p], v = w[2 * p + 1];
            sts128(Wb + ((wsts0 + p * 4096) ^ 64),
                   packhf(u.x, u.y), packhf(u.z, u.w),
                   packhf(v.x, v.y), packhf(v.z, v.w));
        }
        if (m + 1 < NPAIR) {
#pragma unroll
            for (int p = 0; p < 4; p++) {
                w[2 * p]     = *(const int4*)(wpB + p * W_P);
                w[2 * p + 1] = *(const int4*)(wpB + p * W_P + 16);
            }
            wpB += KC * 4;
        }
        __syncthreads();   // W half1 visible
        compute_chunk(Wb, Xb, 64, aOff, bOff, acc);
    }

    // ---- epilogue: ticket-serialized deterministic split-K ----
    if (ksp != 0) {
        if (tid == 0) {
            int v;
            do {
                asm volatile("ld.acquire.gpu.global.b32 %0, [%1];"
                             : "=r"(v) : "l"(g_ticket + tile));
            } while (v != ksp);
        }
        __syncthreads();   // all threads see predecessor's stores (acquire + bar)
    }
    const int g = lane >> 2;
    const int t2 = (lane & 3) * 2;
#pragma unroll
    for (int mi = 0; mi < 2; mi++) {
        const int f0 = row_base + wid * 32 + mi * 16 + g;
#pragma unroll
        for (int n = 0; n < 4; n++) {
            const int tok = n * 8 + t2;
            float* o0 = &out[(size_t)tok * OUTF + f0];
            float* o1 = &out[(size_t)(tok + 1) * OUTF + f0];
            const float* a = acc[mi * 4 + n];
            if (ksp == 0) {
                o0[0] = a[0]; o1[0] = a[1]; o0[8] = a[2]; o1[8] = a[3];
            } else {
                o0[0] += a[0]; o1[0] += a[1]; o0[8] += a[2]; o1[8] += a[3];
            }
        }
    }
    __threadfence();
    __syncthreads();
    if (tid == 0) {
        int nxt = (ksp == KSPLIT - 1) ? 0 : ksp + 1;   // last resets for next replay
        asm volatile("st.release.gpu.global.b32 [%0], %1;"
                     :: "l"(g_ticket + tile), "r"(nxt) : "memory");
    }
}

// ---------------- launch ----------------
extern "C" void kernel_launch(void* const* d_in, const int* in_sizes, int n_in,
                              void* d_out, int out_size) {
    const float* x      = (const float*)d_in[0];
    const int*   weight = (const int*)d_in[1];
    const float* scales = (const float*)d_in[2];
    float*       out    = (float*)d_out;
    (void)in_sizes; (void)n_in; (void)out_size;

    prep_kernel<<<(TOKENS * INF + 255) / 256, 256>>>(x, scales);
    qgemm_kernel<<<NTILES * KSPLIT, NTHR>>>(weight, out);
}

// round 17
// speedup vs baseline: 1.5281x; 1.5281x over previous
#include <cuda_runtime.h>
#include <cuda_fp16.h>
#include <cstdint>

// ---------------------------------------------------------------------------
// out[t,o] = sum_i (x[t,i]*scales[i]) * W[o,i]
//   x [32,4096] f32, W [14336,4096] int32 (int8-valued), scales [4096] f32
//   out [32,14336] f32
//
// R17: R11 (best: TILE_M=64, 128 thr, warp = 16 rows x 32 tokens, KC=64,
// split-K x2, 448 CTAs) + depth-2 W register staging via 2x-unrolled loop
// (named w0/w1 arrays, R6-proven) + __ldcs streaming W loads (read-once,
// evict-first; keeps L2 clean for the 448x-reread xs).
// R15 proved the limiter is exposed DRAM latency in the phase pipeline:
// L1 41.8% / DRAM 46% / issue 10.5% when prefetch distance shrank.
// ---------------------------------------------------------------------------

#define SWZ(off) ((off) ^ (((off) >> 3) & 0x70))

static constexpr int TOKENS = 32;
static constexpr int INF    = 4096;
static constexpr int OUTF   = 14336;
static constexpr int TILE_M = 64;
static constexpr int NTHR   = 128;
static constexpr int KSPLIT = 2;
static constexpr int KHALF  = INF / KSPLIT;     // 2048
static constexpr int KC     = 64;               // K elements per chunk
static constexpr int NITER  = KHALF / KC;       // 32 (even)
static constexpr int NPAIR  = NITER / 2;        // 16

// per-buffer SMEM layout (bytes)
static constexpr int A_BYTES = TILE_M * 128;        // 8192 (64 rows x 128B, SW128)
static constexpr int X_OFF   = A_BYTES;             // xs tile 32 x 64 fp16 = 4096
static constexpr int BUF_BYTES  = A_BYTES + TOKENS * 128;  // 12288
static constexpr int SMEM_TOTAL = 2 * BUF_BYTES;           // 24576

static constexpr int W_P = 16 * INF * 4;      // +16 rows (bytes)
static constexpr int X_P = 16 * INF * 2;      // +16 tokens (bytes)

// fp16 scaled activations (built by prep kernel)
__device__ __align__(16) __half g_xs[TOKENS * INF];

// ---------------- helpers ----------------
__device__ __forceinline__ uint32_t smem_u32(const void* p) {
    uint32_t a;
    asm("{ .reg .u64 t; cvta.to.shared.u64 t, %1; cvt.u32.u64 %0, t; }"
        : "=r"(a) : "l"(p));
    return a;
}

__device__ __forceinline__ void sts128(uint32_t addr, uint32_t r0, uint32_t r1,
                                       uint32_t r2, uint32_t r3) {
    asm volatile("st.shared.v4.b32 [%0], {%1, %2, %3, %4};"
                 :: "r"(addr), "r"(r0), "r"(r1), "r"(r2), "r"(r3) : "memory");
}

__device__ __forceinline__ void cp16(uint32_t dst, const void* src) {
    asm volatile("cp.async.cg.shared.global [%0], [%1], 16;"
                 :: "r"(dst), "l"(src) : "memory");
}
__device__ __forceinline__ void cp_commit() {
    asm volatile("cp.async.commit_group;" ::: "memory");
}
__device__ __forceinline__ void cp_wait0() {
    asm volatile("cp.async.wait_group 0;" ::: "memory");
}

// streaming (evict-first) 16B load — W is read exactly once
__device__ __forceinline__ int4 ldgcs(const void* p) {
    int4 v;
    asm volatile("ld.global.cs.v4.b32 {%0,%1,%2,%3}, [%4];"
                 : "=r"(v.x), "=r"(v.y), "=r"(v.z), "=r"(v.w) : "l"(p));
    return v;
}

// pack two ints (|v|<=127, exact in fp16) -> half2 bits
__device__ __forceinline__ uint32_t packhf(int a, int b) {
    __half2 h = __floats2half2_rn((float)a, (float)b);
    return *reinterpret_cast<uint32_t*>(&h);
}

__device__ __forceinline__ void ldsm_x4(uint32_t addr, uint32_t& r0, uint32_t& r1,
                                        uint32_t& r2, uint32_t& r3) {
    asm volatile("ldmatrix.sync.aligned.m8n8.x4.shared.b16 {%0,%1,%2,%3}, [%4];"
                 : "=r"(r0), "=r"(r1), "=r"(r2), "=r"(r3) : "r"(addr));
}

__device__ __forceinline__ void mma_16816(float* d, const uint32_t* a, const uint32_t* b) {
    asm volatile(
        "mma.sync.aligned.m16n8k16.row.col.f32.f16.f16.f32 "
        "{%0,%1,%2,%3}, {%4,%5,%6,%7}, {%8,%9}, {%0,%1,%2,%3};"
        : "+f"(d[0]), "+f"(d[1]), "+f"(d[2]), "+f"(d[3])
        : "r"(a[0]), "r"(a[1]), "r"(a[2]), "r"(a[3]), "r"(b[0]), "r"(b[1]));
}

// ---------------- prep: xs = fp16(x*scales) + zero the output ----------------
static constexpr int OUT_ELEMS = TOKENS * OUTF;        // 458752
static constexpr int OUT_VEC4  = OUT_ELEMS / 4;        // 114688

__global__ void prep_kernel(const float* __restrict__ x, const float* __restrict__ s,
                            float4* __restrict__ out4) {
    int i = blockIdx.x * blockDim.x + threadIdx.x;
    if (i < TOKENS * INF) {
        int k = i & (INF - 1);
        g_xs[i] = __float2half_rn(x[i] * s[k]);
    }
    if (i < OUT_VEC4) {
        out4[i] = make_float4(0.f, 0.f, 0.f, 0.f);
    }
}

// ---------------- main GEMM ----------------
__global__ void __launch_bounds__(NTHR, 3)
qgemm_kernel(const int* __restrict__ W, float* __restrict__ out) {
    __shared__ __align__(1024) char smem[SMEM_TOTAL];
    const uint32_t sb = smem_u32(smem);
    const int tid = threadIdx.x;
    const int lane = tid & 31;
    const int wid = tid >> 5;      // 0..3 -> row group (16 rows each)

    const int tile = blockIdx.x >> 1;
    const int kbase = (blockIdx.x & 1) * KHALF;
    const int row_base = tile * TILE_M;

    // ---- W producer: 4 granules (16B fp16 = 2 int4 src); rows m0+16p ----
    const int m0 = tid >> 3;             // 0..15
    const int c0 = tid & 7;              // 0..7
    const char* wpB = (const char*)(W + (size_t)(row_base + m0) * INF + kbase + c0 * 8);
    const uint32_t wsts0 = SWZ(m0 * 128 + c0 * 16);     // +p*2048 per granule (exact)

    // ---- xs producer: 2 granules of 8 fp16 per thread ----
    const char* xpA;
    const char* xpB;
    uint32_t xstsA, xstsB;
    {
        int t0 = tid >> 3, cc0 = tid & 7;             // tokens 0..15
        xpA = (const char*)(g_xs + t0 * INF + kbase + cc0 * 8);
        xpB = xpA + X_P;                              // tokens 16..31
        xstsA = X_OFF + SWZ(t0 * 128 + cc0 * 16);
        xstsB = xstsA + 2048;
    }

    // ---- ldmatrix lane geometry ----
    const int rowA   = wid * 16 + (lane & 7) + (lane & 8);
    const int aCsel  = (lane & 16);             // +8 fp16 cols -> +16 bytes
    const int tokBlo = (lane & 7) + ((lane & 16) >> 1);     // tokens 0-15 group
    const int bCsel  = (lane & 8) * 2;          // +16 bytes for k+8 tile
    const int aOff   = rowA * 128 + aCsel;
    const int bOffLo = tokBlo * 128 + bCsel;
    const int bOffHi = bOffLo + 16 * 128;       // tokens 16-31

    float acc[4][4];
#pragma unroll
    for (int n = 0; n < 4; n++)
#pragma unroll
        for (int r = 0; r < 4; r++) acc[n][r] = 0.0f;

    // depth-2 W staging: NAMED arrays, constant indices only (R5/R6 lesson)
    int4 w0[8], w1[8];

    // ---- prologue: W chunks 0,1 -> regs; xs chunk 0 -> cp.async ----
#pragma unroll
    for (int p = 0; p < 4; p++) {
        w0[2 * p]     = ldgcs(wpB + p * W_P);
        w0[2 * p + 1] = ldgcs(wpB + p * W_P + 16);
    }
    wpB += KC * 4;
#pragma unroll
    for (int p = 0; p < 4; p++) {
        w1[2 * p]     = ldgcs(wpB + p * W_P);
        w1[2 * p + 1] = ldgcs(wpB + p * W_P + 16);
    }
    wpB += KC * 4;

    cp16(sb + xstsA, xpA); xpA += KC * 2;
    cp16(sb + xstsB, xpB); xpB += KC * 2;
    cp_commit();

    const uint32_t buf0 = sb;
    const uint32_t buf1 = sb + BUF_BYTES;

#pragma unroll 1
    for (int itp = 0; itp < NPAIR; ++itp) {
        // ================= even chunk e = 2*itp, buffer 0 =================
        {
#pragma unroll
            for (int p = 0; p < 4; p++) {
                int4 u = w0[2 * p], v = w0[2 * p + 1];
                sts128(buf0 + wsts0 + p * 2048,
                       packhf(u.x, u.y), packhf(u.z, u.w),
                       packhf(v.x, v.y), packhf(v.z, v.w));
            }
            // refill w0 from chunk e+2 (two full chunk-periods of cover)
            if (itp + 1 < NPAIR) {
#pragma unroll
                for (int p = 0; p < 4; p++) {
                    w0[2 * p]     = ldgcs(wpB + p * W_P);
                    w0[2 * p + 1] = ldgcs(wpB + p * W_P + 16);
                }
                wpB += KC * 4;
            }

            cp_wait0();        // xs(e) landed in buf0
            __syncthreads();   // buf0 tile visible; prior buf1 readers done

            // xs(e+1) -> buf1
            cp16(buf1 + xstsA, xpA); xpA += KC * 2;
            cp16(buf1 + xstsB, xpB); xpB += KC * 2;
            cp_commit();

            // compute buf0: 4 k16-steps; 1 A-ldsm + 2 B-ldsm + 4 MMA each
#pragma unroll
            for (int ks = 0; ks < 4; ks++) {
                uint32_t a[4], bl[4], bh[4];
                const int kb = ks * 32;
                ldsm_x4(buf0 + SWZ(aOff + kb), a[0], a[1], a[2], a[3]);
                ldsm_x4(buf0 + X_OFF + SWZ(bOffLo + kb), bl[0], bl[1], bl[2], bl[3]);
                mma_16816(acc[0], a, bl + 0);
                mma_16816(acc[1], a, bl + 2);
                ldsm_x4(buf0 + X_OFF + SWZ(bOffHi + kb), bh[0], bh[1], bh[2], bh[3]);
                mma_16816(acc[2], a, bh + 0);
                mma_16816(acc[3], a, bh + 2);
            }
        }
        // ================= odd chunk o = e+1, buffer 1 =================
        {
#pragma unroll
            for (int p = 0; p < 4; p++) {
                int4 u = w1[2 * p], v = w1[2 * p + 1];
                sts128(buf1 + wsts0 + p * 2048,
                       packhf(u.x, u.y), packhf(u.z, u.w),
                       packhf(v.x, v.y), packhf(v.z, v.w));
            }
            // refill w1 from chunk o+2
            if (itp + 1 < NPAIR) {
#pragma unroll
                for (int p = 0; p < 4; p++) {
                    w1[2 * p]     = ldgcs(wpB + p * W_P);
                    w1[2 * p + 1] = ldgcs(wpB + p * W_P + 16);
                }
                wpB += KC * 4;
            }

            cp_wait0();        // xs(o) landed in buf1
            __syncthreads();   // buf1 tile visible; buf0 readers done

            // xs(o+1) -> buf0
            if (itp + 1 < NPAIR) {
                cp16(buf0 + xstsA, xpA); xpA += KC * 2;
                cp16(buf0 + xstsB, xpB); xpB += KC * 2;
                cp_commit();
            }

            // compute buf1
#pragma unroll
            for (int ks = 0; ks < 4; ks++) {
                uint32_t a[4], bl[4], bh[4];
                const int kb = ks * 32;
                ldsm_x4(buf1 + SWZ(aOff + kb), a[0], a[1], a[2], a[3]);
                ldsm_x4(buf1 + X_OFF + SWZ(bOffLo + kb), bl[0], bl[1], bl[2], bl[3]);
                mma_16816(acc[0], a, bl + 0);
                mma_16816(acc[1], a, bl + 2);
                ldsm_x4(buf1 + X_OFF + SWZ(bOffHi + kb), bh[0], bh[1], bh[2], bh[3]);
                mma_16816(acc[2], a, bh + 0);
                mma_16816(acc[3], a, bh + 2);
            }
        }
    }

    // ---- epilogue: atomicAdd partials (2 deterministic contributors/elem) ----
    const int g = lane >> 2;
    const int t2 = (lane & 3) * 2;
    const int f0 = row_base + wid * 16 + g;
#pragma unroll
    for (int nt = 0; nt < 4; nt++) {
        const int tok = nt * 8 + t2;
        atomicAdd(&out[(size_t)tok * OUTF + f0],           acc[nt][0]);
        atomicAdd(&out[(size_t)(tok + 1) * OUTF + f0],     acc[nt][1]);
        atomicAdd(&out[(size_t)tok * OUTF + f0 + 8],       acc[nt][2]);
        atomicAdd(&out[(size_t)(tok + 1) * OUTF + f0 + 8], acc[nt][3]);
    }
}

// ---------------- launch ----------------
extern "C" void kernel_launch(void* const* d_in, const int* in_sizes, int n_in,
                              void* d_out, int out_size) {
    const float* x      = (const float*)d_in[0];
    const int*   weight = (const int*)d_in[1];
    const float* scales = (const float*)d_in[2];
    float*       out    = (float*)d_out;
    (void)in_sizes; (void)n_in; (void)out_size;

    prep_kernel<<<(TOKENS * INF + 255) / 256, 256>>>(x, scales, (float4*)out);
    qgemm_kernel<<<(OUTF / TILE_M) * KSPLIT, NTHR>>>(weight, out);
}